// round 3
// baseline (speedup 1.0000x reference)
#include <cuda_runtime.h>
#include <math.h>

#define S_DIM   32768          // W*H*Z = 32*32*32
#define SH_DIM  16384          // pooled spatial (z/2)
#define C_DIM   256
#define CI_DIM  128
#define BATCH   4

// ---------------- scratch (device globals: no runtime allocation) ----------------
__device__ float d_Wt1[256 * 384];          // transposed stacked [g;theta;phi] weights: [c][o]
__device__ float d_Bs1[384];                // stacked biases
__device__ float d_Wt2[128 * 256];          // transposed w_w: [ci][co]
__device__ float d_th [BATCH * CI_DIM * S_DIM];    // theta(x), full z
__device__ float d_gp [BATCH * CI_DIM * SH_DIM];   // g(x) pooled
__device__ float d_php[BATCH * CI_DIM * SH_DIM];   // phi(x) pooled
__device__ float d_y  [BATCH * CI_DIM * S_DIM];    // attention output
__device__ float d_wy [BATCH * C_DIM  * S_DIM];    // W conv output
__device__ float d_scale[256];
__device__ float d_shift[256];

// ---------------- prep: transpose weights for coalesced GEMM loads ----------------
__global__ void prep_kernel(const float* __restrict__ g_w,  const float* __restrict__ th_w,
                            const float* __restrict__ ph_w, const float* __restrict__ g_b,
                            const float* __restrict__ th_b, const float* __restrict__ ph_b,
                            const float* __restrict__ w_w) {
    int i = blockIdx.x * 256 + threadIdx.x;
    if (i < 98304) {                         // Wt1[c*384 + o] = W_o[o%128][c]
        int c = i / 384, o = i % 384;
        const float* src = (o < 128) ? g_w : (o < 256 ? th_w : ph_w);
        int oo = o & 127;
        d_Wt1[i] = src[oo * 256 + c];
    }
    if (i < 32768) {                         // Wt2[ci*256 + co] = w_w[co][ci]
        int ci = i / 256, co = i % 256;
        d_Wt2[i] = w_w[co * 128 + ci];
    }
    if (i < 384) {
        d_Bs1[i] = (i < 128) ? g_b[i] : (i < 256 ? th_b[i - 128] : ph_b[i - 256]);
    }
}

// ---------------- tiled GEMM: OUT(o,s) = sum_c Wt[c][o] * X[c][s] ------------------
// 128(o) x 128(s) tile, K-step 8, fp32 FFMA accumulators (8x8 per thread).
// MODE 0: fused 3-conv on input x; blockIdx.x selects {g(pooled), theta(full), phi(pooled)}.
// MODE 1: W conv; X is the DEVICE-GLOBAL d_y (referenced in device code — never
//         passed from host; passing a __device__ symbol from host gives the host
//         shadow address, which GB300's ATS silently reads as zeros).
template <int KDIM, int LDW, int MODE>
__global__ void __launch_bounds__(256, 2)
gemm_kernel(const float* __restrict__ Xparam, const float* __restrict__ bias_g) {
    __shared__ float Ws[8][128];
    __shared__ float Xs[8][128];

    const int ot = blockIdx.x;
    const int st = blockIdx.y;
    const int b  = blockIdx.z;

    const float* Xbase = (MODE == 0) ? Xparam : (const float*)d_y;
    const float* X = Xbase + (size_t)b * KDIM * S_DIM + (size_t)st * 128;
    const float* W = (MODE == 0 ? d_Wt1 : d_Wt2) + ot * 128;

    const int tid = threadIdx.x;
    const int tx = tid & 15, ty = tid >> 4;
    const int lo = tid & 127;
    const int lk = (tid >> 7) * 4;

    float acc[8][8];
#pragma unroll
    for (int i = 0; i < 8; i++)
#pragma unroll
        for (int j = 0; j < 8; j++) acc[i][j] = 0.f;

    float rw[4], rx[4];
#pragma unroll
    for (int r = 0; r < 4; r++) {
        rw[r] = W[(size_t)(lk + r) * LDW + lo];
        rx[r] = X[(size_t)(lk + r) * S_DIM + lo];
    }

    for (int k0 = 0; k0 < KDIM; k0 += 8) {
#pragma unroll
        for (int r = 0; r < 4; r++) {
            Ws[lk + r][lo] = rw[r];
            Xs[lk + r][lo] = rx[r];
        }
        __syncthreads();
        if (k0 + 8 < KDIM) {
#pragma unroll
            for (int r = 0; r < 4; r++) {
                rw[r] = W[(size_t)(k0 + 8 + lk + r) * LDW + lo];
                rx[r] = X[(size_t)(k0 + 8 + lk + r) * S_DIM + lo];
            }
        }
#pragma unroll
        for (int kk = 0; kk < 8; kk++) {
            float4 a0 = *(const float4*)&Ws[kk][ty * 8];
            float4 a1 = *(const float4*)&Ws[kk][ty * 8 + 4];
            float4 b0 = *(const float4*)&Xs[kk][tx * 8];
            float4 b1 = *(const float4*)&Xs[kk][tx * 8 + 4];
            float av[8] = {a0.x, a0.y, a0.z, a0.w, a1.x, a1.y, a1.z, a1.w};
            float bv[8] = {b0.x, b0.y, b0.z, b0.w, b1.x, b1.y, b1.z, b1.w};
#pragma unroll
            for (int i = 0; i < 8; i++)
#pragma unroll
                for (int j = 0; j < 8; j++)
                    acc[i][j] = fmaf(av[i], bv[j], acc[i][j]);
        }
        __syncthreads();
    }

    const int oo = ty * 8;
    const int ss = st * 128 + tx * 8;

    if (MODE == 0) {
#pragma unroll
        for (int i = 0; i < 8; i++) {
            float bia = d_Bs1[ot * 128 + oo + i];
            if (ot == 1) {  // theta: full z
                float* dst = d_th + ((size_t)(b * 128 + oo + i)) * S_DIM + ss;
#pragma unroll
                for (int j = 0; j < 4; j++) {
                    float2 v = make_float2(acc[i][2 * j] + bia, acc[i][2 * j + 1] + bia);
                    *(float2*)(dst + 2 * j) = v;
                }
            } else {        // g / phi: maxpool over consecutive z pairs
                float* dst = (ot == 0 ? d_gp : d_php) +
                             ((size_t)(b * 128 + oo + i)) * SH_DIM + (ss >> 1);
#pragma unroll
                for (int j = 0; j < 4; j++) {
                    dst[j] = fmaxf(acc[i][2 * j], acc[i][2 * j + 1]) + bia;
                }
            }
        }
    } else {
#pragma unroll
        for (int i = 0; i < 8; i++) {
            int o = ot * 128 + oo + i;
            float bia = bias_g[o];
            float* dst = d_wy + ((size_t)(b * 256 + o)) * S_DIM + ss;
#pragma unroll
            for (int j = 0; j < 4; j++) {
                float2 v = make_float2(acc[i][2 * j] + bia, acc[i][2 * j + 1] + bia);
                *(float2*)(dst + 2 * j) = v;
            }
        }
    }
}

// ---------------- attention: per (b,w,h) group --------------------------------------
// f(z,y) = sum_c th[c][z]*ph[c][y]; softmax over y; y_out[c][z] = sum_y attn[z][y]*g[c][y]
__global__ void __launch_bounds__(128) attn_kernel() {
    __shared__ float th_s[128 * 32];
    __shared__ float ph_s[128 * 17];   // padded rows (conflict-free strided reads)
    __shared__ float g_s [128 * 17];
    __shared__ float f_s [32 * 16];

    const int grp = blockIdx.x;
    const int b   = grp >> 10;
    const int wh  = grp & 1023;
    const int tid = threadIdx.x;

    {   // theta tile: 128 rows x 32 floats
        const float* base = d_th + (size_t)(b * 128) * S_DIM + wh * 32;
        for (int i = tid; i < 1024; i += 128) {
            int c = i >> 3, q = i & 7;
            float4 v = *(const float4*)(base + (size_t)c * S_DIM + q * 4);
            *(float4*)&th_s[c * 32 + q * 4] = v;
        }
    }
    {   // pooled g / phi tiles: 128 rows x 16 floats (scalar STS into padded rows)
        const float* gb = d_gp  + (size_t)(b * 128) * SH_DIM + wh * 16;
        const float* pb = d_php + (size_t)(b * 128) * SH_DIM + wh * 16;
        for (int i = tid; i < 512; i += 128) {
            int c = i >> 2, q = (i & 3) * 4;
            float4 gv = *(const float4*)(gb + (size_t)c * SH_DIM + q);
            float4 pv = *(const float4*)(pb + (size_t)c * SH_DIM + q);
            int o = c * 17 + q;
            g_s[o + 0] = gv.x; g_s[o + 1] = gv.y; g_s[o + 2] = gv.z; g_s[o + 3] = gv.w;
            ph_s[o + 0] = pv.x; ph_s[o + 1] = pv.y; ph_s[o + 2] = pv.z; ph_s[o + 3] = pv.w;
        }
    }
    __syncthreads();

    {   // f: each thread computes 4 y values for one z
        const int z = tid >> 2, y0 = (tid & 3) * 4;
        float fv0 = 0.f, fv1 = 0.f, fv2 = 0.f, fv3 = 0.f;
#pragma unroll 8
        for (int c = 0; c < 128; c++) {
            float t = th_s[c * 32 + z];
            fv0 += t * ph_s[c * 17 + y0 + 0];
            fv1 += t * ph_s[c * 17 + y0 + 1];
            fv2 += t * ph_s[c * 17 + y0 + 2];
            fv3 += t * ph_s[c * 17 + y0 + 3];
        }
        f_s[z * 16 + y0 + 0] = fv0;
        f_s[z * 16 + y0 + 1] = fv1;
        f_s[z * 16 + y0 + 2] = fv2;
        f_s[z * 16 + y0 + 3] = fv3;
    }
    __syncthreads();

    if (tid < 32) {   // softmax over y per z-row
        int z = tid;
        float m = -1e30f;
#pragma unroll
        for (int y = 0; y < 16; y++) m = fmaxf(m, f_s[z * 16 + y]);
        float sum = 0.f;
#pragma unroll
        for (int y = 0; y < 16; y++) {
            float e = __expf(f_s[z * 16 + y] - m);
            f_s[z * 16 + y] = e;
            sum += e;
        }
        float inv = 1.f / sum;
#pragma unroll
        for (int y = 0; y < 16; y++) f_s[z * 16 + y] *= inv;
    }
    __syncthreads();

    {   // y_out: one channel row per thread
        const int c = tid;
        float yv[32];
#pragma unroll
        for (int z = 0; z < 32; z++) {
            float acc = 0.f;
#pragma unroll
            for (int y = 0; y < 16; y++) acc += f_s[z * 16 + y] * g_s[c * 17 + y];
            yv[z] = acc;
        }
        float* dst = d_y + (size_t)(b * 128 + c) * S_DIM + wh * 32;
#pragma unroll
        for (int q = 0; q < 8; q++)
            *(float4*)(dst + q * 4) = make_float4(yv[q * 4], yv[q * 4 + 1], yv[q * 4 + 2], yv[q * 4 + 3]);
    }
}

// ---------------- BN stats: per-channel mean/var over (b, spatial) -------------------
__global__ void __launch_bounds__(256) bn_stats(const float* __restrict__ gamma,
                                                const float* __restrict__ beta) {
    const int c = blockIdx.x;
    const int tid = threadIdx.x;
    float s = 0.f, s2 = 0.f;
    for (int i = tid; i < (BATCH * S_DIM) / 4; i += 256) {
        int e  = i * 4;
        int b  = e >> 15;
        int sp = e & (S_DIM - 1);
        float4 v = *(const float4*)&d_wy[((size_t)(b * 256 + c)) * S_DIM + sp];
        s  += v.x + v.y + v.z + v.w;
        s2 += v.x * v.x + v.y * v.y + v.z * v.z + v.w * v.w;
    }
    __shared__ float sh[256], sh2[256];
    sh[tid] = s; sh2[tid] = s2;
    __syncthreads();
    for (int off = 128; off > 0; off >>= 1) {
        if (tid < off) { sh[tid] += sh[tid + off]; sh2[tid] += sh2[tid + off]; }
        __syncthreads();
    }
    if (tid == 0) {
        float n = (float)(BATCH * S_DIM);
        float mean = sh[0] / n;
        float var  = sh2[0] / n - mean * mean;
        float inv  = rsqrtf(var + 1e-5f);
        float sc   = gamma[c] * inv;
        d_scale[c] = sc;
        d_shift[c] = beta[c] - mean * sc;
    }
}

// ---------------- BN apply + residual -------------------------------------------------
__global__ void __launch_bounds__(256) bn_apply(const float* __restrict__ x,
                                                float* __restrict__ out) {
    size_t i = (size_t)blockIdx.x * 256 + threadIdx.x;   // float4 index
    size_t e = i * 4;
    int c = (int)((e >> 15) & 255);
    float4 w  = *(const float4*)&d_wy[e];
    float4 xv = *(const float4*)(x + e);
    float sc = d_scale[c], sf = d_shift[c];
    float4 o;
    o.x = w.x * sc + sf + xv.x;
    o.y = w.y * sc + sf + xv.y;
    o.z = w.z * sc + sf + xv.z;
    o.w = w.w * sc + sf + xv.w;
    *(float4*)(out + e) = o;
}

// ---------------- launch ---------------------------------------------------------------
extern "C" void kernel_launch(void* const* d_in, const int* in_sizes, int n_in,
                              void* d_out, int out_size) {
    const float* x     = (const float*)d_in[0];
    const float* g_w   = (const float*)d_in[1];
    const float* g_b   = (const float*)d_in[2];
    const float* th_w  = (const float*)d_in[3];
    const float* th_b  = (const float*)d_in[4];
    const float* ph_w  = (const float*)d_in[5];
    const float* ph_b  = (const float*)d_in[6];
    const float* w_w   = (const float*)d_in[7];
    const float* w_b   = (const float*)d_in[8];
    const float* gamma = (const float*)d_in[9];
    const float* beta  = (const float*)d_in[10];
    float* out = (float*)d_out;

    prep_kernel<<<384, 256>>>(g_w, th_w, ph_w, g_b, th_b, ph_b, w_w);

    // fused g/theta/phi conv (+ z-maxpool for g, phi)
    gemm_kernel<256, 384, 0><<<dim3(3, 256, BATCH), 256>>>(x, nullptr);

    // attention per (b,w,h) group
    attn_kernel<<<BATCH * 1024, 128>>>();

    // W conv: CI -> C  (X = d_y, resolved INSIDE device code)
    gemm_kernel<128, 256, 1><<<dim3(2, 256, BATCH), 256>>>(nullptr, w_b);

    // batchnorm (training-mode batch stats) + residual
    bn_stats<<<256, 256>>>(gamma, beta);
    bn_apply<<<32768, 256>>>(x, out);
}